// round 15
// baseline (speedup 1.0000x reference)
#include <cuda_runtime.h>
#include <cuda_bf16.h>
#include <cstdint>

#define B_  16
#define T_  512
#define H_  2048
#define TH_ (T_ * H_)        // 1048576
#define WLD 4096             // W row stride (floats)
#define NBLK 128

// ---------------- device globals -------------------------------------------
__device__ unsigned g_bar2[4 * T_];

__device__ __nv_bfloat16 g_xh[(size_t)B_ * T_ * H_];
__device__ __nv_bfloat16 g_xl[(size_t)B_ * T_ * H_];
__device__ __nv_bfloat16 g_wxh[(size_t)H_ * H_];
__device__ __nv_bfloat16 g_wxl[(size_t)H_ * H_];
__device__ __nv_bfloat16 g_whh[(size_t)H_ * H_];
__device__ __nv_bfloat16 g_whl[(size_t)H_ * H_];

__global__ void zero_bar_kernel() {
    int i = blockIdx.x * blockDim.x + threadIdx.x;
    if (i < 4 * T_) g_bar2[i] = 0u;
}

// ---------------- helpers ---------------------------------------------------
__device__ __forceinline__ uint32_t smem_u32(const void* p) {
    return (uint32_t)__cvta_generic_to_shared(p);
}
__device__ __forceinline__ void cp16(uint32_t s, const void* g) {
    asm volatile("cp.async.cg.shared.global [%0], [%1], 16;" :: "r"(s), "l"(g));
}
#define CP_COMMIT() asm volatile("cp.async.commit_group;")

__device__ __forceinline__ void ldsm4(uint32_t (&r)[4], uint32_t addr) {
    asm volatile("ldmatrix.sync.aligned.m8n8.x4.shared.b16 {%0,%1,%2,%3}, [%4];"
                 : "=r"(r[0]), "=r"(r[1]), "=r"(r[2]), "=r"(r[3]) : "r"(addr));
}
__device__ __forceinline__ void mma16816(float (&c)[4], const uint32_t (&a)[4],
                                         uint32_t b0, uint32_t b1) {
    asm volatile("mma.sync.aligned.m16n8k16.row.col.f32.bf16.bf16.f32 "
                 "{%0,%1,%2,%3}, {%4,%5,%6,%7}, {%8,%9}, {%0,%1,%2,%3};"
                 : "+f"(c[0]), "+f"(c[1]), "+f"(c[2]), "+f"(c[3])
                 : "r"(a[0]), "r"(a[1]), "r"(a[2]), "r"(a[3]), "r"(b0), "r"(b1));
}
__device__ __forceinline__ float4 ld_cg4(const float* p) {
    float4 v;
    asm volatile("ld.global.cg.v4.f32 {%0,%1,%2,%3}, [%4];"
                 : "=f"(v.x), "=f"(v.y), "=f"(v.z), "=f"(v.w) : "l"(p));
    return v;
}
__device__ __forceinline__ void red_add_v2(float* p, float a, float b) {
    asm volatile("red.global.add.v2.f32 [%0], {%1, %2};"
                 :: "l"(p), "f"(a), "f"(b) : "memory");
}
// packed bf16x2 convert: result = {bf16(hi_arg) <<16 | bf16(lo_arg)}
__device__ __forceinline__ uint32_t cvt_bf16x2(float hi_arg, float lo_arg) {
    uint32_t r;
    asm("cvt.rn.bf16x2.f32 %0, %1, %2;" : "=r"(r) : "f"(hi_arg), "f"(lo_arg));
    return r;
}

// ---------------- prepass: hi/lo bf16 splits (one kernel) --------------------
#define XB ((B_ * T_ * H_ / 4) / 256)      // 16384
#define WB ((H_ * H_ / 4) / 256)           // 4096

__global__ void split_xw_kernel(const float* __restrict__ x,
                                const float* __restrict__ W)
{
    int bb = blockIdx.x;
    if (bb < XB) {
        size_t fi = (size_t)bb * 256 + threadIdx.x;
        float4 v = *(const float4*)(x + fi * 4);
        union { __nv_bfloat16 b[4]; uint2 u; } hh, ll;
        float f[4] = {v.x, v.y, v.z, v.w};
#pragma unroll
        for (int i = 0; i < 4; i++) {
            hh.b[i] = __float2bfloat16_rn(f[i]);
            ll.b[i] = __float2bfloat16_rn(f[i] - __bfloat162float(hh.b[i]));
        }
        *(uint2*)(g_xh + fi * 4) = hh.u;
        *(uint2*)(g_xl + fi * 4) = ll.u;
    } else {
        size_t fi = (size_t)(bb - XB) * 256 + threadIdx.x;
        int g = (int)(fi >> 9);
        int c = (int)(fi & 511) * 4;
        const float* base = W + (size_t)g * WLD;

        float4 v = *(const float4*)(base + c);
        union { __nv_bfloat16 b[4]; uint2 u; } hh, ll;
        float f[4] = {v.x, v.y, v.z, v.w};
#pragma unroll
        for (int i = 0; i < 4; i++) {
            hh.b[i] = __float2bfloat16_rn(f[i]);
            ll.b[i] = __float2bfloat16_rn(f[i] - __bfloat162float(hh.b[i]));
        }
        *(uint2*)(g_wxh + (size_t)g * H_ + c) = hh.u;
        *(uint2*)(g_wxl + (size_t)g * H_ + c) = ll.u;

        v = *(const float4*)(base + H_ + c);
        float f2[4] = {v.x, v.y, v.z, v.w};
#pragma unroll
        for (int i = 0; i < 4; i++) {
            hh.b[i] = __float2bfloat16_rn(f2[i]);
            ll.b[i] = __float2bfloat16_rn(f2[i] - __bfloat162float(hh.b[i]));
        }
        *(uint2*)(g_whh + (size_t)g * H_ + c) = hh.u;
        *(uint2*)(g_whl + (size_t)g * H_ + c) = ll.u;
    }
}

// ===========================================================================
// Phase 1: u[m,g] = sum_k x[m,k] W[g,k] + b[g], FUSED 3x bf16 split mma.
// 128x128x32 tiles; per chunk load Ah/Al/Bh/Bl once, issue all 3 products.
// (R14 exact — measured ~610us)
// ===========================================================================
#define P1_ST 40
#define P1_TILE (128 * P1_ST)
#define P1_STAGE (4 * P1_TILE)
#define P1_SMEM_BYTES (2 * P1_STAGE * 2)   // 81920

__global__ __launch_bounds__(256, 2)
void gemm_u_mma(const float* __restrict__ bias, float* __restrict__ out)
{
    extern __shared__ __align__(16) __nv_bfloat16 sm[];

    const int tid = threadIdx.x, lane = tid & 31, wid = tid >> 5;
    const int m0 = blockIdx.y * 128, g0 = blockIdx.x * 128;
    const int wm = wid & 3, wn = wid >> 2;

    const int lrow = tid >> 1;
    const int lco  = (tid & 1) * 16;

    float acc[2][8][4];
#pragma unroll
    for (int i = 0; i < 2; i++)
#pragma unroll
        for (int j = 0; j < 8; j++)
#pragma unroll
            for (int q = 0; q < 4; q++) acc[i][j][q] = 0.0f;

#define P1F_ISSUE(st, it) do {                                                 \
        int _kk = (it) * 32;                                                   \
        __nv_bfloat16* _s = sm + (st) * P1_STAGE;                              \
        uint32_t _sa = smem_u32(_s + lrow * P1_ST + lco);                      \
        const __nv_bfloat16* _g;                                               \
        _g = g_xh  + (size_t)(m0 + lrow) * H_ + _kk + lco;                     \
        cp16(_sa, _g); cp16(_sa + 16, _g + 8);                                 \
        _g = g_xl  + (size_t)(m0 + lrow) * H_ + _kk + lco;                     \
        cp16(_sa + 2 * P1_TILE, _g); cp16(_sa + 2 * P1_TILE + 16, _g + 8);     \
        _g = g_wxh + (size_t)(g0 + lrow) * H_ + _kk + lco;                     \
        cp16(_sa + 4 * P1_TILE, _g); cp16(_sa + 4 * P1_TILE + 16, _g + 8);     \
        _g = g_wxl + (size_t)(g0 + lrow) * H_ + _kk + lco;                     \
        cp16(_sa + 6 * P1_TILE, _g); cp16(_sa + 6 * P1_TILE + 16, _g + 8);     \
    } while (0)

    P1F_ISSUE(0, 0); CP_COMMIT();

    const int NT = 64;
    for (int it = 0; it < NT; ++it) {
        if (it + 1 < NT) {
            P1F_ISSUE((it + 1) & 1, it + 1); CP_COMMIT();
            asm volatile("cp.async.wait_group 1;");
        } else {
            asm volatile("cp.async.wait_group 0;");
        }
        __syncthreads();

        const __nv_bfloat16* S  = sm + (it & 1) * P1_STAGE;
        const __nv_bfloat16* Ah = S;
        const __nv_bfloat16* Al = S + P1_TILE;
        const __nv_bfloat16* Bh = S + 2 * P1_TILE;
        const __nv_bfloat16* Bl = S + 3 * P1_TILE;

#pragma unroll
        for (int kq = 0; kq < 2; kq++) {
            const int arow = wm * 32 + (lane & 15);
            const int acol = kq * 16 + ((lane >> 4) << 3);
            const int brow = wn * 64 + (lane & 7) + ((lane & 16) >> 1);
            const int bcol = kq * 16 + (lane & 8);

            uint32_t ah[2][4], al[2][4];
#pragma unroll
            for (int mt = 0; mt < 2; mt++) {
                ldsm4(ah[mt], smem_u32(Ah + (arow + mt * 16) * P1_ST + acol));
                ldsm4(al[mt], smem_u32(Al + (arow + mt * 16) * P1_ST + acol));
            }
            {
                uint32_t bf[4][4];
#pragma unroll
                for (int ng = 0; ng < 4; ng++)
                    ldsm4(bf[ng], smem_u32(Bh + (brow + ng * 16) * P1_ST + bcol));
#pragma unroll
                for (int mt = 0; mt < 2; mt++)
#pragma unroll
                    for (int ng = 0; ng < 4; ng++) {
                        mma16816(acc[mt][2 * ng],     ah[mt], bf[ng][0], bf[ng][1]);
                        mma16816(acc[mt][2 * ng + 1], ah[mt], bf[ng][2], bf[ng][3]);
                        mma16816(acc[mt][2 * ng],     al[mt], bf[ng][0], bf[ng][1]);
                        mma16816(acc[mt][2 * ng + 1], al[mt], bf[ng][2], bf[ng][3]);
                    }
            }
            {
                uint32_t bf[4][4];
#pragma unroll
                for (int ng = 0; ng < 4; ng++)
                    ldsm4(bf[ng], smem_u32(Bl + (brow + ng * 16) * P1_ST + bcol));
#pragma unroll
                for (int mt = 0; mt < 2; mt++)
#pragma unroll
                    for (int ng = 0; ng < 4; ng++) {
                        mma16816(acc[mt][2 * ng],     ah[mt], bf[ng][0], bf[ng][1]);
                        mma16816(acc[mt][2 * ng + 1], ah[mt], bf[ng][2], bf[ng][3]);
                    }
            }
        }
        __syncthreads();
    }

    const int r0 = lane >> 2, c0 = (lane & 3) * 2;
#pragma unroll
    for (int mt = 0; mt < 2; mt++) {
        int m = m0 + wm * 32 + mt * 16 + r0;
#pragma unroll
        for (int nt = 0; nt < 8; nt++) {
            int g = g0 + wn * 64 + nt * 8 + c0;
            float bx = bias[g], by = bias[g + 1];
            float2 v0 = { acc[mt][nt][0] + bx, acc[mt][nt][1] + by };
            float2 v1 = { acc[mt][nt][2] + bx, acc[mt][nt][3] + by };
            *(float2*)(out + (size_t)m * H_ + g)       = v0;
            *(float2*)(out + (size_t)(m + 8) * H_ + g) = v1;
        }
    }
}

// ===========================================================================
// Phase 2: persistent scan. Warp tile = n8 x FULL K512: no intra-block
// reduction (each output has one owner warp). 3 syncs/step.
// Grid 128 = 32 g-tiles (64) x 4 k-tiles (512). Wh frags in registers.
// 3 accumulators (AhBh / AhBl / AlBh) keep HMMA chains at depth 32.
// bf16x2 packed convert for the h split.
// ===========================================================================
#define GT 64
#define KT 512
#define WST 520
#define HST 520
#define O_HH  0
#define O_HL  (B_ * HST)
#define SC_SMEM_BYTES (2 * GT * WST * 2)   // 133120

__global__ __launch_bounds__(256, 1)
void rnn_scan(float* __restrict__ out)
{
    extern __shared__ __align__(16) __nv_bfloat16 sm[];
    __nv_bfloat16* whh_s = sm;                 // staging (dead after preload)
    __nv_bfloat16* whl_s = sm + GT * WST;
    __nv_bfloat16* hh_s  = sm + O_HH;          // overlays staging
    __nv_bfloat16* hl_s  = sm + O_HL;

    const int tid = threadIdx.x, lane = tid & 31, wid = tid >> 5;
    const int gi = blockIdx.x & 31;
    const int ki = blockIdx.x >> 5;
    const int g0 = gi * GT;
    const int k0 = ki * KT;

    // ---- stage Wh hi/lo slice: 64 g-rows x 512 k ----
    for (int i = tid; i < GT * (KT / 8); i += 256) {
        int row = i >> 6;
        int c8  = (i & 63) * 8;
        *(uint4*)(whh_s + row * WST + c8) =
            *(const uint4*)(g_whh + (size_t)(g0 + row) * H_ + k0 + c8);
        *(uint4*)(whl_s + row * WST + c8) =
            *(const uint4*)(g_whl + (size_t)(g0 + row) * H_ + k0 + c8);
    }
    __syncthreads();

    // ---- preload B fragments: n8 (warp wid) x k512, hi+lo = 128 regs ----
    uint32_t Bh[16][4], Bl[16][4];
    {
        const int br = wid * 8 + (lane & 7);
        const uint32_t baseH = smem_u32(whh_s + br * WST + (lane >> 3) * 8);
        const uint32_t baseL = smem_u32(whl_s + br * WST + (lane >> 3) * 8);
#pragma unroll
        for (int ch = 0; ch < 16; ch++) {
            ldsm4(Bh[ch], baseH + ch * 64);
            ldsm4(Bl[ch], baseL + ch * 64);
        }
    }
    __syncthreads();   // preload done before staging area is overwritten by h

    const int r0 = lane >> 2, c0 = (lane & 3) * 2;
    const uint32_t aHb = smem_u32(hh_s + (lane & 15) * HST + ((lane >> 4) << 3));
    const uint32_t aLb = smem_u32(hl_s + (lane & 15) * HST + ((lane >> 4) << 3));

    unsigned* mybar = &g_bar2[(gi >> 3) * T_];
    unsigned* wtbar = &g_bar2[ki * T_];

    for (int t = 1; t < T_; ++t) {
        // ---- wait for the 32 producers of my k-slice (also WAR guard) ----
        if (t >= 2) {
            if (tid == 0) {
                unsigned v;
                do {
                    asm volatile("ld.acquire.gpu.global.u32 %0, [%1];"
                                 : "=r"(v) : "l"(wtbar + (t - 1)) : "memory");
                } while (v < 32u);
            }
            __syncthreads();                         // sync A
        }

        // ---- load h_{t-1} k-slice (16 x 512 fp32), packed split to smem ----
#pragma unroll
        for (int r = 0; r < 8; r++) {
            int fi = tid + r * 256;
            int b  = fi >> 7;
            int c4 = fi & 127;
            float4 h4 = ld_cg4(out + (size_t)b * TH_ + (size_t)(t - 1) * H_ + k0 + c4 * 4);
            uint32_t hi01 = cvt_bf16x2(h4.y, h4.x);
            uint32_t hi23 = cvt_bf16x2(h4.w, h4.z);
            float l0 = h4.x - __uint_as_float(hi01 << 16);
            float l1 = h4.y - __uint_as_float(hi01 & 0xFFFF0000u);
            float l2 = h4.z - __uint_as_float(hi23 << 16);
            float l3 = h4.w - __uint_as_float(hi23 & 0xFFFF0000u);
            uint2 hv = { hi01, hi23 };
            uint2 lv = { cvt_bf16x2(l1, l0), cvt_bf16x2(l3, l2) };
            *(uint2*)(hh_s + b * HST + c4 * 4) = hv;
            *(uint2*)(hl_s + b * HST + c4 * 4) = lv;
        }
        __syncthreads();                             // sync B

        // ---- compute: 16 k32 chunks; A from smem, B from registers ----
        float accA[4], accB[4], accC[4];
#pragma unroll
        for (int q = 0; q < 4; q++) { accA[q] = 0.0f; accB[q] = 0.0f; accC[q] = 0.0f; }

#pragma unroll
        for (int ch = 0; ch < 16; ch++) {
            const uint32_t off = ch * 64;
            uint32_t ah0[4], ah1[4], al0[4], al1[4];
            ldsm4(ah0, aHb + off);
            ldsm4(ah1, aHb + off + 32);
            ldsm4(al0, aLb + off);
            ldsm4(al1, aLb + off + 32);
            mma16816(accA, ah0, Bh[ch][0], Bh[ch][1]);
            mma16816(accA, ah1, Bh[ch][2], Bh[ch][3]);
            mma16816(accB, ah0, Bl[ch][0], Bl[ch][1]);
            mma16816(accB, ah1, Bl[ch][2], Bl[ch][3]);
            mma16816(accC, al0, Bh[ch][0], Bh[ch][1]);
            mma16816(accC, al1, Bh[ch][2], Bh[ch][3]);
        }

        // ---- epilogue: direct REDs (single owner per element) ----
        {
            float s0 = accA[0] + accB[0] + accC[0];
            float s1 = accA[1] + accB[1] + accC[1];
            float s2 = accA[2] + accB[2] + accC[2];
            float s3 = accA[3] + accB[3] + accC[3];
            const int gcol = g0 + wid * 8 + c0;
            red_add_v2(out + (size_t)r0 * TH_ + (size_t)t * H_ + gcol, s0, s1);
            red_add_v2(out + (size_t)(r0 + 8) * TH_ + (size_t)t * H_ + gcol, s2, s3);
        }

        // ---- publish ----
        __syncthreads();                             // sync C
        if (t < T_ - 1 && tid == 0) {
            asm volatile("red.release.gpu.global.add.u32 [%0], 1;"
                         :: "l"(mybar + t) : "memory");
        }
    }
}

// ---------------- h_last copy ----------------------------------------------
__global__ void hlast_kernel(const float* __restrict__ out,
                             float* __restrict__ hlast)
{
    int i = blockIdx.x * blockDim.x + threadIdx.x;
    if (i < B_ * H_) {
        int b = i / H_;
        int g = i % H_;
        hlast[i] = out[(size_t)b * TH_ + (size_t)(T_ - 1) * H_ + g];
    }
}

// ---------------- launch ----------------------------------------------------
extern "C" void kernel_launch(void* const* d_in, const int* in_sizes, int n_in,
                              void* d_out, int out_size)
{
    const float* x  = (const float*)d_in[0];
    const float* W  = (const float*)d_in[1];
    const float* bi = (const float*)d_in[2];
    float* out = (float*)d_out;

    cudaFuncSetAttribute(gemm_u_mma,
                         cudaFuncAttributeMaxDynamicSharedMemorySize,
                         P1_SMEM_BYTES);
    cudaFuncSetAttribute(rnn_scan,
                         cudaFuncAttributeMaxDynamicSharedMemorySize,
                         SC_SMEM_BYTES);

    zero_bar_kernel<<<(4 * T_ + 255) / 256, 256>>>();
    split_xw_kernel<<<XB + WB, 256>>>(x, W);

    dim3 ggrid(H_ / 128, (B_ * T_) / 128);   // (16, 64)
    gemm_u_mma<<<ggrid, 256, P1_SMEM_BYTES>>>(bi, out);

    rnn_scan<<<NBLK, 256, SC_SMEM_BYTES>>>(out);

    if (out_size >= B_ * T_ * H_ + B_ * H_) {
        hlast_kernel<<<(B_ * H_ + 255) / 256, 256>>>(out, out + (size_t)B_ * T_ * H_);
    }
}

// round 16
// speedup vs baseline: 1.0096x; 1.0096x over previous
#include <cuda_runtime.h>
#include <cuda_bf16.h>
#include <cstdint>

#define B_  16
#define T_  512
#define H_  2048
#define TH_ (T_ * H_)        // 1048576
#define WLD 4096             // W row stride (floats)
#define NBLK 128

// ---------------- device globals -------------------------------------------
// per-g-tile step counters: g_bar3[gi*T + t] counts the 4 k-split blocks of
// g-tile gi that finished their REDs for step t (count to 4).
__device__ unsigned g_bar3[32 * T_];

__device__ __nv_bfloat16 g_xh[(size_t)B_ * T_ * H_];
__device__ __nv_bfloat16 g_xl[(size_t)B_ * T_ * H_];
__device__ __nv_bfloat16 g_wxh[(size_t)H_ * H_];
__device__ __nv_bfloat16 g_wxl[(size_t)H_ * H_];
__device__ __nv_bfloat16 g_whh[(size_t)H_ * H_];
__device__ __nv_bfloat16 g_whl[(size_t)H_ * H_];

__global__ void zero_bar_kernel() {
    int i = blockIdx.x * blockDim.x + threadIdx.x;
    if (i < 32 * T_) g_bar3[i] = 0u;
}

// ---------------- helpers ---------------------------------------------------
__device__ __forceinline__ uint32_t smem_u32(const void* p) {
    return (uint32_t)__cvta_generic_to_shared(p);
}
__device__ __forceinline__ void cp16(uint32_t s, const void* g) {
    asm volatile("cp.async.cg.shared.global [%0], [%1], 16;" :: "r"(s), "l"(g));
}
#define CP_COMMIT() asm volatile("cp.async.commit_group;")

__device__ __forceinline__ void ldsm4(uint32_t (&r)[4], uint32_t addr) {
    asm volatile("ldmatrix.sync.aligned.m8n8.x4.shared.b16 {%0,%1,%2,%3}, [%4];"
                 : "=r"(r[0]), "=r"(r[1]), "=r"(r[2]), "=r"(r[3]) : "r"(addr));
}
__device__ __forceinline__ void mma16816(float (&c)[4], const uint32_t (&a)[4],
                                         uint32_t b0, uint32_t b1) {
    asm volatile("mma.sync.aligned.m16n8k16.row.col.f32.bf16.bf16.f32 "
                 "{%0,%1,%2,%3}, {%4,%5,%6,%7}, {%8,%9}, {%0,%1,%2,%3};"
                 : "+f"(c[0]), "+f"(c[1]), "+f"(c[2]), "+f"(c[3])
                 : "r"(a[0]), "r"(a[1]), "r"(a[2]), "r"(a[3]), "r"(b0), "r"(b1));
}
__device__ __forceinline__ float4 ld_cg4(const float* p) {
    float4 v;
    asm volatile("ld.global.cg.v4.f32 {%0,%1,%2,%3}, [%4];"
                 : "=f"(v.x), "=f"(v.y), "=f"(v.z), "=f"(v.w) : "l"(p));
    return v;
}
__device__ __forceinline__ void red_add_v2(float* p, float a, float b) {
    asm volatile("red.global.add.v2.f32 [%0], {%1, %2};"
                 :: "l"(p), "f"(a), "f"(b) : "memory");
}
// packed bf16x2 convert: result = {bf16(hi_arg)<<16 | bf16(lo_arg)}
__device__ __forceinline__ uint32_t cvt_bf16x2(float hi_arg, float lo_arg) {
    uint32_t r;
    asm("cvt.rn.bf16x2.f32 %0, %1, %2;" : "=r"(r) : "f"(hi_arg), "f"(lo_arg));
    return r;
}

// ---------------- prepass: hi/lo bf16 splits (one kernel) --------------------
#define XB ((B_ * T_ * H_ / 4) / 256)      // 16384
#define WB ((H_ * H_ / 4) / 256)           // 4096

__global__ void split_xw_kernel(const float* __restrict__ x,
                                const float* __restrict__ W)
{
    int bb = blockIdx.x;
    if (bb < XB) {
        size_t fi = (size_t)bb * 256 + threadIdx.x;
        float4 v = *(const float4*)(x + fi * 4);
        union { __nv_bfloat16 b[4]; uint2 u; } hh, ll;
        float f[4] = {v.x, v.y, v.z, v.w};
#pragma unroll
        for (int i = 0; i < 4; i++) {
            hh.b[i] = __float2bfloat16_rn(f[i]);
            ll.b[i] = __float2bfloat16_rn(f[i] - __bfloat162float(hh.b[i]));
        }
        *(uint2*)(g_xh + fi * 4) = hh.u;
        *(uint2*)(g_xl + fi * 4) = ll.u;
    } else {
        size_t fi = (size_t)(bb - XB) * 256 + threadIdx.x;
        int g = (int)(fi >> 9);
        int c = (int)(fi & 511) * 4;
        const float* base = W + (size_t)g * WLD;

        float4 v = *(const float4*)(base + c);
        union { __nv_bfloat16 b[4]; uint2 u; } hh, ll;
        float f[4] = {v.x, v.y, v.z, v.w};
#pragma unroll
        for (int i = 0; i < 4; i++) {
            hh.b[i] = __float2bfloat16_rn(f[i]);
            ll.b[i] = __float2bfloat16_rn(f[i] - __bfloat162float(hh.b[i]));
        }
        *(uint2*)(g_wxh + (size_t)g * H_ + c) = hh.u;
        *(uint2*)(g_wxl + (size_t)g * H_ + c) = ll.u;

        v = *(const float4*)(base + H_ + c);
        float f2[4] = {v.x, v.y, v.z, v.w};
#pragma unroll
        for (int i = 0; i < 4; i++) {
            hh.b[i] = __float2bfloat16_rn(f2[i]);
            ll.b[i] = __float2bfloat16_rn(f2[i] - __bfloat162float(hh.b[i]));
        }
        *(uint2*)(g_whh + (size_t)g * H_ + c) = hh.u;
        *(uint2*)(g_whl + (size_t)g * H_ + c) = ll.u;
    }
}

// ===========================================================================
// Phase 1: u[m,g] = sum_k x[m,k] W[g,k] + b[g], FUSED 3x bf16 split mma.
// (R14 exact — measured ~610us)
// ===========================================================================
#define P1_ST 40
#define P1_TILE (128 * P1_ST)
#define P1_STAGE (4 * P1_TILE)
#define P1_SMEM_BYTES (2 * P1_STAGE * 2)   // 81920

__global__ __launch_bounds__(256, 2)
void gemm_u_mma(const float* __restrict__ bias, float* __restrict__ out)
{
    extern __shared__ __align__(16) __nv_bfloat16 sm[];

    const int tid = threadIdx.x, lane = tid & 31, wid = tid >> 5;
    const int m0 = blockIdx.y * 128, g0 = blockIdx.x * 128;
    const int wm = wid & 3, wn = wid >> 2;

    const int lrow = tid >> 1;
    const int lco  = (tid & 1) * 16;

    float acc[2][8][4];
#pragma unroll
    for (int i = 0; i < 2; i++)
#pragma unroll
        for (int j = 0; j < 8; j++)
#pragma unroll
            for (int q = 0; q < 4; q++) acc[i][j][q] = 0.0f;

#define P1F_ISSUE(st, it) do {                                                 \
        int _kk = (it) * 32;                                                   \
        __nv_bfloat16* _s = sm + (st) * P1_STAGE;                              \
        uint32_t _sa = smem_u32(_s + lrow * P1_ST + lco);                      \
        const __nv_bfloat16* _g;                                               \
        _g = g_xh  + (size_t)(m0 + lrow) * H_ + _kk + lco;                     \
        cp16(_sa, _g); cp16(_sa + 16, _g + 8);                                 \
        _g = g_xl  + (size_t)(m0 + lrow) * H_ + _kk + lco;                     \
        cp16(_sa + 2 * P1_TILE, _g); cp16(_sa + 2 * P1_TILE + 16, _g + 8);     \
        _g = g_wxh + (size_t)(g0 + lrow) * H_ + _kk + lco;                     \
        cp16(_sa + 4 * P1_TILE, _g); cp16(_sa + 4 * P1_TILE + 16, _g + 8);     \
        _g = g_wxl + (size_t)(g0 + lrow) * H_ + _kk + lco;                     \
        cp16(_sa + 6 * P1_TILE, _g); cp16(_sa + 6 * P1_TILE + 16, _g + 8);     \
    } while (0)

    P1F_ISSUE(0, 0); CP_COMMIT();

    const int NT = 64;
    for (int it = 0; it < NT; ++it) {
        if (it + 1 < NT) {
            P1F_ISSUE((it + 1) & 1, it + 1); CP_COMMIT();
            asm volatile("cp.async.wait_group 1;");
        } else {
            asm volatile("cp.async.wait_group 0;");
        }
        __syncthreads();

        const __nv_bfloat16* S  = sm + (it & 1) * P1_STAGE;
        const __nv_bfloat16* Ah = S;
        const __nv_bfloat16* Al = S + P1_TILE;
        const __nv_bfloat16* Bh = S + 2 * P1_TILE;
        const __nv_bfloat16* Bl = S + 3 * P1_TILE;

#pragma unroll
        for (int kq = 0; kq < 2; kq++) {
            const int arow = wm * 32 + (lane & 15);
            const int acol = kq * 16 + ((lane >> 4) << 3);
            const int brow = wn * 64 + (lane & 7) + ((lane & 16) >> 1);
            const int bcol = kq * 16 + (lane & 8);

            uint32_t ah[2][4], al[2][4];
#pragma unroll
            for (int mt = 0; mt < 2; mt++) {
                ldsm4(ah[mt], smem_u32(Ah + (arow + mt * 16) * P1_ST + acol));
                ldsm4(al[mt], smem_u32(Al + (arow + mt * 16) * P1_ST + acol));
            }
            {
                uint32_t bf[4][4];
#pragma unroll
                for (int ng = 0; ng < 4; ng++)
                    ldsm4(bf[ng], smem_u32(Bh + (brow + ng * 16) * P1_ST + bcol));
#pragma unroll
                for (int mt = 0; mt < 2; mt++)
#pragma unroll
                    for (int ng = 0; ng < 4; ng++) {
                        mma16816(acc[mt][2 * ng],     ah[mt], bf[ng][0], bf[ng][1]);
                        mma16816(acc[mt][2 * ng + 1], ah[mt], bf[ng][2], bf[ng][3]);
                        mma16816(acc[mt][2 * ng],     al[mt], bf[ng][0], bf[ng][1]);
                        mma16816(acc[mt][2 * ng + 1], al[mt], bf[ng][2], bf[ng][3]);
                    }
            }
            {
                uint32_t bf[4][4];
#pragma unroll
                for (int ng = 0; ng < 4; ng++)
                    ldsm4(bf[ng], smem_u32(Bl + (brow + ng * 16) * P1_ST + bcol));
#pragma unroll
                for (int mt = 0; mt < 2; mt++)
#pragma unroll
                    for (int ng = 0; ng < 4; ng++) {
                        mma16816(acc[mt][2 * ng],     ah[mt], bf[ng][0], bf[ng][1]);
                        mma16816(acc[mt][2 * ng + 1], ah[mt], bf[ng][2], bf[ng][3]);
                    }
            }
        }
        __syncthreads();
    }

    const int r0 = lane >> 2, c0 = (lane & 3) * 2;
#pragma unroll
    for (int mt = 0; mt < 2; mt++) {
        int m = m0 + wm * 32 + mt * 16 + r0;
#pragma unroll
        for (int nt = 0; nt < 8; nt++) {
            int g = g0 + wn * 64 + nt * 8 + c0;
            float bx = bias[g], by = bias[g + 1];
            float2 v0 = { acc[mt][nt][0] + bx, acc[mt][nt][1] + by };
            float2 v1 = { acc[mt][nt][2] + bx, acc[mt][nt][3] + by };
            *(float2*)(out + (size_t)m * H_ + g)       = v0;
            *(float2*)(out + (size_t)(m + 8) * H_ + g) = v1;
        }
    }
}

// ===========================================================================
// Phase 2: persistent scan (R14 compute core) + per-g-tile fine-grained sync.
// Grid 128 = 32 g-tiles (64) x 4 k-tiles (512).
// Warp w waits ONLY on g-tile 8ki+w (count 4) then loads+converts its own
// 64-col chunk -> straggler wait overlaps the h load/convert.
// Compute: 8 warps = 4 n-groups (n16) x 2 k-halves (k256), Wh frags in regs.
// ===========================================================================
#define GT 64
#define KT 512
#define WST 520
#define HST 520
#define O_HH  0
#define O_HL  (B_ * HST)
#define O_RED (2 * B_ * HST)
#define SC_SMEM_BYTES (2 * GT * WST * 2)   // 133120

__global__ __launch_bounds__(256, 1)
void rnn_scan(float* __restrict__ out)
{
    extern __shared__ __align__(16) __nv_bfloat16 sm[];
    __nv_bfloat16* whh_s = sm;                 // staging (dead after preload)
    __nv_bfloat16* whl_s = sm + GT * WST;
    __nv_bfloat16* hh_s  = sm + O_HH;          // overlays staging
    __nv_bfloat16* hl_s  = sm + O_HL;
    float* red = (float*)(sm + O_RED);

    const int tid = threadIdx.x, lane = tid & 31, wid = tid >> 5;
    const int gi = blockIdx.x & 31;
    const int ki = blockIdx.x >> 5;
    const int g0 = gi * GT;
    const int k0 = ki * KT;

    const int wn = wid >> 1;           // n-group 0..3 (16 cols each)
    const int kg = wid & 1;            // k-half 0/1 (256 each)

    // ---- stage Wh hi/lo slice: 64 g-rows x 512 k ----
    for (int i = tid; i < GT * (KT / 8); i += 256) {
        int row = i >> 6;
        int c8  = (i & 63) * 8;
        *(uint4*)(whh_s + row * WST + c8) =
            *(const uint4*)(g_whh + (size_t)(g0 + row) * H_ + k0 + c8);
        *(uint4*)(whl_s + row * WST + c8) =
            *(const uint4*)(g_whl + (size_t)(g0 + row) * H_ + k0 + c8);
    }
    __syncthreads();

    // ---- preload B fragments into registers: n16 x k256, hi+lo ----
    uint32_t Bh[2][8][4], Bl[2][8][4];
#pragma unroll
    for (int nt = 0; nt < 2; nt++) {
        const int br = wn * 16 + nt * 8 + (lane & 7);
        const uint32_t baseH = smem_u32(whh_s + br * WST + kg * 256 + (lane >> 3) * 8);
        const uint32_t baseL = smem_u32(whl_s + br * WST + kg * 256 + (lane >> 3) * 8);
#pragma unroll
        for (int ch = 0; ch < 8; ch++) {
            ldsm4(Bh[nt][ch], baseH + ch * 64);
            ldsm4(Bl[nt][ch], baseL + ch * 64);
        }
    }
    __syncthreads();   // preload done before staging area is overwritten by h

    const int r0 = lane >> 2, c0 = (lane & 3) * 2;
    const uint32_t aHb = smem_u32(hh_s + (lane & 15) * HST + ((lane >> 4) << 3));
    const uint32_t aLb = smem_u32(hl_s + (lane & 15) * HST + ((lane >> 4) << 3));

    unsigned* mybar = &g_bar3[gi * T_];                   // producer arrival
    unsigned* wtbar = &g_bar3[(8 * ki + wid) * T_];       // this warp's wait

    for (int t = 1; t < T_; ++t) {
        // ---- per-warp wait: my 64-col chunk's g-tile done step t-1 ----
        if (t >= 2) {
            if (lane == 0) {
                unsigned v;
                do {
                    asm volatile("ld.acquire.gpu.global.u32 %0, [%1];"
                                 : "=r"(v) : "l"(wtbar + (t - 1)) : "memory");
                } while (v < 4u);
            }
            __syncwarp();
        }

        // ---- load my chunk: 16 rows x 64 cols fp32, packed split to smem ----
        {
            const float* src = out + (size_t)(t - 1) * H_ + k0 + wid * 64;
#pragma unroll
            for (int p = 0; p < 8; p++) {
                int fi = lane + p * 32;            // 0..255 float4s
                int b  = fi >> 4;                  // 0..15
                int c4 = fi & 15;                  // 0..15
                float4 h4 = ld_cg4(src + (size_t)b * TH_ + c4 * 4);
                uint32_t hi01 = cvt_bf16x2(h4.y, h4.x);
                uint32_t hi23 = cvt_bf16x2(h4.w, h4.z);
                float l0 = h4.x - __uint_as_float(hi01 << 16);
                float l1 = h4.y - __uint_as_float(hi01 & 0xFFFF0000u);
                float l2 = h4.z - __uint_as_float(hi23 << 16);
                float l3 = h4.w - __uint_as_float(hi23 & 0xFFFF0000u);
                uint2 hv = { hi01, hi23 };
                uint2 lv = { cvt_bf16x2(l1, l0), cvt_bf16x2(l3, l2) };
                *(uint2*)(hh_s + b * HST + wid * 64 + c4 * 4) = hv;
                *(uint2*)(hl_s + b * HST + wid * 64 + c4 * 4) = lv;
            }
        }
        __syncthreads();                           // sync B: full h slice in smem

        // ---- compute: 8 k32 chunks; A from smem, B from registers ----
        float accA[2][4], accB[2][4];
#pragma unroll
        for (int i = 0; i < 2; i++)
#pragma unroll
            for (int q = 0; q < 4; q++) { accA[i][q] = 0.0f; accB[i][q] = 0.0f; }

#pragma unroll
        for (int ch = 0; ch < 8; ch++) {
            const uint32_t off = kg * 512 + ch * 64;
            uint32_t ah0[4], ah1[4], al0[4], al1[4];
            ldsm4(ah0, aHb + off);
            ldsm4(ah1, aHb + off + 32);
            ldsm4(al0, aLb + off);
            ldsm4(al1, aLb + off + 32);
#pragma unroll
            for (int nt = 0; nt < 2; nt++) {
                mma16816(accA[nt], ah0, Bh[nt][ch][0], Bh[nt][ch][1]);
                mma16816(accA[nt], ah1, Bh[nt][ch][2], Bh[nt][ch][3]);
                mma16816(accB[nt], ah0, Bl[nt][ch][0], Bl[nt][ch][1]);
                mma16816(accB[nt], ah1, Bl[nt][ch][2], Bl[nt][ch][3]);
                mma16816(accB[nt], al0, Bh[nt][ch][0], Bh[nt][ch][1]);
                mma16816(accB[nt], al1, Bh[nt][ch][2], Bh[nt][ch][3]);
            }
        }

        // ---- k-half reduction via smem: kg=1 stores ----
        float* rw = red + (wn * 32 + lane) * 8;
        if (kg == 1) {
#pragma unroll
            for (int nt = 0; nt < 2; nt++) {
                float4 v = { accA[nt][0] + accB[nt][0], accA[nt][1] + accB[nt][1],
                             accA[nt][2] + accB[nt][2], accA[nt][3] + accB[nt][3] };
                *(float4*)(rw + nt * 4) = v;
            }
        }
        __syncthreads();                           // mid sync

        if (kg == 0) {
#pragma unroll
            for (int nt = 0; nt < 2; nt++) {
                float4 v = *(const float4*)(rw + nt * 4);
                float s0 = accA[nt][0] + accB[nt][0] + v.x;
                float s1 = accA[nt][1] + accB[nt][1] + v.y;
                float s2 = accA[nt][2] + accB[nt][2] + v.z;
                float s3 = accA[nt][3] + accB[nt][3] + v.w;
                const int gcol = g0 + wn * 16 + nt * 8 + c0;
                red_add_v2(out + (size_t)r0 * TH_ + (size_t)t * H_ + gcol, s0, s1);
                red_add_v2(out + (size_t)(r0 + 8) * TH_ + (size_t)t * H_ + gcol, s2, s3);
            }
        }

        // ---- publish: arrive at my g-tile counter for step t ----
        __syncthreads();                           // sync C: REDs issued, smem free
        if (t < T_ - 1 && tid == 0) {
            asm volatile("red.release.gpu.global.add.u32 [%0], 1;"
                         :: "l"(mybar + t) : "memory");
        }
    }
}

// ---------------- h_last copy ----------------------------------------------
__global__ void hlast_kernel(const float* __restrict__ out,
                             float* __restrict__ hlast)
{
    int i = blockIdx.x * blockDim.x + threadIdx.x;
    if (i < B_ * H_) {
        int b = i / H_;
        int g = i % H_;
        hlast[i] = out[(size_t)b * TH_ + (size_t)(T_ - 1) * H_ + g];
    }
}

// ---------------- launch ----------------------------------------------------
extern "C" void kernel_launch(void* const* d_in, const int* in_sizes, int n_in,
                              void* d_out, int out_size)
{
    const float* x  = (const float*)d_in[0];
    const float* W  = (const float*)d_in[1];
    const float* bi = (const float*)d_in[2];
    float* out = (float*)d_out;

    cudaFuncSetAttribute(gemm_u_mma,
                         cudaFuncAttributeMaxDynamicSharedMemorySize,
                         P1_SMEM_BYTES);
    cudaFuncSetAttribute(rnn_scan,
                         cudaFuncAttributeMaxDynamicSharedMemorySize,
                         SC_SMEM_BYTES);

    zero_bar_kernel<<<(32 * T_ + 255) / 256, 256>>>();
    split_xw_kernel<<<XB + WB, 256>>>(x, W);

    dim3 ggrid(H_ / 128, (B_ * T_) / 128);   // (16, 64)
    gemm_u_mma<<<ggrid, 256, P1_SMEM_BYTES>>>(bi, out);

    rnn_scan<<<NBLK, 256, SC_SMEM_BYTES>>>(out);

    if (out_size >= B_ * T_ * H_ + B_ * H_) {
        hlast_kernel<<<(B_ * H_ + 255) / 256, 256>>>(out, out + (size_t)B_ * T_ * H_);
    }
}